// round 5
// baseline (speedup 1.0000x reference)
#include <cuda_runtime.h>
#include <math.h>
#include <stdint.h>

#define NN 20000
#define EE 160000
#define ET (EE + NN)
#define DIM 768
#define IND 2304
#define CLS 32
#define EPS_BN 1e-5f
#define SLOPE 0.2f

// ---------------- scratch (device globals; no allocation) ----------------
__device__ float g_xl[(size_t)NN * DIM];
__device__ float g_h1[(size_t)NN * DIM];
__device__ float g_al[NN];
__device__ float g_ar[NN];
__device__ float g_stats[2 * IND];
__device__ float g_scale[IND];
__device__ float g_shift[IND];
__device__ int   g_deg[NN];
__device__ int   g_off[NN + 1];
__device__ int   g_cur[NN];
__device__ int   g_srcs[ET];
__device__ float g_acc[8];

// ---------------- init: zero deg/stats/acc ----------------
__global__ void init_k() {
    int i = blockIdx.x * blockDim.x + threadIdx.x;
    if (i < NN) g_deg[i] = 0;
    if (i < 2 * IND) g_stats[i] = 0.f;
    if (i < 8) g_acc[i] = 0.f;
}

// ---------------- BatchNorm stats ----------------
__global__ void bn_stats_k(const float* __restrict__ x) {
    int c = blockIdx.x * blockDim.x + threadIdx.x;
    if (c >= IND) return;
    int r0 = blockIdx.y * 128;
    int r1 = min(r0 + 128, NN);
    float s = 0.f, s2 = 0.f;
    for (int r = r0; r < r1; r++) {
        float v = x[(size_t)r * IND + c];
        s += v; s2 += v * v;
    }
    atomicAdd(&g_stats[c], s);
    atomicAdd(&g_stats[IND + c], s2);
}
__global__ void bn_finalize_k(const float* __restrict__ gamma, const float* __restrict__ beta) {
    int c = blockIdx.x * blockDim.x + threadIdx.x;
    if (c >= IND) return;
    float mu = g_stats[c] / (float)NN;
    float var = g_stats[IND + c] / (float)NN - mu * mu;
    float inv = 1.f / sqrtf(var + EPS_BN);
    float sc = gamma[c] * inv;
    g_scale[c] = sc;
    g_shift[c] = beta[c] - mu * sc;
}

// ---------------- tf32 helpers ----------------
__device__ __forceinline__ uint32_t f2tf(float f) {
    uint32_t u;
    asm("cvt.rna.tf32.f32 %0, %1;" : "=r"(u) : "f"(f));
    return u;
}
__device__ __forceinline__ void mma_tf32(float* d, const uint32_t* a, const uint32_t* b) {
    asm volatile(
        "mma.sync.aligned.m16n8k8.row.col.f32.tf32.tf32.f32 "
        "{%0,%1,%2,%3},{%4,%5,%6,%7},{%8,%9},{%0,%1,%2,%3};"
        : "+f"(d[0]), "+f"(d[1]), "+f"(d[2]), "+f"(d[3])
        : "r"(a[0]), "r"(a[1]), "r"(a[2]), "r"(a[3]), "r"(b[0]), "r"(b[1]));
}

// ---------------- 3xTF32 GEMM, software-pipelined, optional BN fold on A ----
// C[M,N] = [A1;A2][M, K1+K2] @ B[K1+K2, N]; bn1/bn2: apply scale/shift to A cols.
// BM=128, BN=128, BK=16. 128 threads = 4 warps (2x2), warp tile 64x64.
#define AST 20
__global__ void __launch_bounds__(128)
tf32gemm3x_k(const float* __restrict__ A1, int K1, int bn1,
             const float* __restrict__ A2, int K2, int bn2,
             const float* __restrict__ B, float* __restrict__ C,
             int M, int N) {
    __shared__ uint32_t AsH[128 * AST];
    __shared__ uint32_t AsL[128 * AST];
    __shared__ uint32_t BsH[16 * 128];
    __shared__ uint32_t BsL[16 * 128];
    const int tid = threadIdx.x;
    const int wid = tid >> 5, lane = tid & 31;
    const int bm0 = blockIdx.y * 128, bn0 = blockIdx.x * 128;
    const int wm0 = (wid >> 1) * 64;
    const int wn0 = (wid & 1) * 64;
    const int r0 = lane >> 2, c0 = lane & 3;
    const int bsw = c0 * 8;

    float acc[4][8][4];
#pragma unroll
    for (int i = 0; i < 4; i++)
#pragma unroll
        for (int j = 0; j < 8; j++)
#pragma unroll
            for (int v = 0; v < 4; v++) acc[i][j][v] = 0.f;

    float4 pa[4], pb[4];  // register staging for next tile

    const int KT = (K1 + K2) / 16;

    auto ldg_tile = [&](int kt) {
        const int k0 = kt * 16;
        const float* Ap; int lda, ka, bn;
        if (k0 < K1) { Ap = A1; lda = K1; ka = k0; bn = bn1; }
        else         { Ap = A2; lda = K2; ka = k0 - K1; bn = bn2; }
#pragma unroll
        for (int it = 0; it < 4; it++) {
            int idx = it * 128 + tid;
            int m = idx >> 2, kc = (idx & 3) * 4;
            float4 v = make_float4(0.f, 0.f, 0.f, 0.f);
            int gr = bm0 + m;
            if (gr < M) {
                v = *(const float4*)(Ap + (size_t)gr * lda + ka + kc);
                if (bn) {
                    float4 sc = *(const float4*)(g_scale + ka + kc);
                    float4 sh = *(const float4*)(g_shift + ka + kc);
                    v.x = fmaf(v.x, sc.x, sh.x);
                    v.y = fmaf(v.y, sc.y, sh.y);
                    v.z = fmaf(v.z, sc.z, sh.z);
                    v.w = fmaf(v.w, sc.w, sh.w);
                }
            }
            pa[it] = v;
        }
#pragma unroll
        for (int it = 0; it < 4; it++) {
            int idx = it * 128 + tid;
            int kk = idx >> 5, n4 = (idx & 31) * 4;
            pb[it] = *(const float4*)(B + (size_t)(k0 + kk) * N + bn0 + n4);
        }
    };
    auto sts_tile = [&]() {
#pragma unroll
        for (int it = 0; it < 4; it++) {
            int idx = it * 128 + tid;
            int m = idx >> 2, kc = (idx & 3) * 4;
            float4 v = pa[it];
            uint4 h, l;
            h.x = f2tf(v.x); l.x = f2tf(v.x - __uint_as_float(h.x));
            h.y = f2tf(v.y); l.y = f2tf(v.y - __uint_as_float(h.y));
            h.z = f2tf(v.z); l.z = f2tf(v.z - __uint_as_float(h.z));
            h.w = f2tf(v.w); l.w = f2tf(v.w - __uint_as_float(h.w));
            *(uint4*)(&AsH[m * AST + kc]) = h;
            *(uint4*)(&AsL[m * AST + kc]) = l;
        }
#pragma unroll
        for (int it = 0; it < 4; it++) {
            int idx = it * 128 + tid;
            int kk = idx >> 5, n4 = (idx & 31) * 4;
            int col = n4 ^ ((kk & 3) * 8);
            float4 v = pb[it];
            uint4 h, l;
            h.x = f2tf(v.x); l.x = f2tf(v.x - __uint_as_float(h.x));
            h.y = f2tf(v.y); l.y = f2tf(v.y - __uint_as_float(h.y));
            h.z = f2tf(v.z); l.z = f2tf(v.z - __uint_as_float(h.z));
            h.w = f2tf(v.w); l.w = f2tf(v.w - __uint_as_float(h.w));
            *(uint4*)(&BsH[kk * 128 + col]) = h;
            *(uint4*)(&BsL[kk * 128 + col]) = l;
        }
    };

    // prologue
    ldg_tile(0);
    sts_tile();
    __syncthreads();

    for (int kt = 0; kt < KT; kt++) {
        if (kt + 1 < KT) ldg_tile(kt + 1);  // prefetch next tile into regs

        // compute on current smem tile
#pragma unroll
        for (int sub = 0; sub < 2; sub++) {
            const int kb = sub * 8;
            uint32_t ah[4][4], al_[4][4];
#pragma unroll
            for (int mt = 0; mt < 4; mt++) {
                int ra = (wm0 + mt * 16 + r0) * AST + kb + c0;
                int rb = ra + 8 * AST;
                ah[mt][0] = AsH[ra];     al_[mt][0] = AsL[ra];
                ah[mt][1] = AsH[rb];     al_[mt][1] = AsL[rb];
                ah[mt][2] = AsH[ra + 4]; al_[mt][2] = AsL[ra + 4];
                ah[mt][3] = AsH[rb + 4]; al_[mt][3] = AsL[rb + 4];
            }
#pragma unroll
            for (int half = 0; half < 2; half++) {
                uint32_t bh[4][2], bl[4][2];
#pragma unroll
                for (int q = 0; q < 4; q++) {
                    int nt = half * 4 + q;
                    int nb = (wn0 + nt * 8 + r0) ^ bsw;
                    int i0 = (kb + c0) * 128 + nb;
                    int i1 = i0 + 4 * 128;
                    bh[q][0] = BsH[i0]; bl[q][0] = BsL[i0];
                    bh[q][1] = BsH[i1]; bl[q][1] = BsL[i1];
                }
#pragma unroll
                for (int mt = 0; mt < 4; mt++)
#pragma unroll
                    for (int q = 0; q < 4; q++) {
                        float* a = acc[mt][half * 4 + q];
                        mma_tf32(a, al_[mt], bh[q]);
                        mma_tf32(a, ah[mt], bl[q]);
                        mma_tf32(a, ah[mt], bh[q]);
                    }
            }
        }
        __syncthreads();
        if (kt + 1 < KT) sts_tile();
        __syncthreads();
    }

    // epilogue
#pragma unroll
    for (int mt = 0; mt < 4; mt++) {
        int gr0 = bm0 + wm0 + mt * 16 + r0;
        int gr1 = gr0 + 8;
#pragma unroll
        for (int nt = 0; nt < 8; nt++) {
            int gc = bn0 + wn0 + nt * 8 + 2 * c0;
            if (gr0 < M)
                *(float2*)(C + (size_t)gr0 * N + gc) = make_float2(acc[mt][nt][0], acc[mt][nt][1]);
            if (gr1 < M)
                *(float2*)(C + (size_t)gr1 * N + gc) = make_float2(acc[mt][nt][2], acc[mt][nt][3]);
        }
    }
}

// ---------------- SIMT SGEMM (small-N heads), optional BN fold on A ----------
template<int BM, int BN, int BK, int TM, int TN, bool BNA>
__global__ void __launch_bounds__((BM / TM) * (BN / TN))
sgemm_k(const float* __restrict__ A, const float* __restrict__ B,
        const float* __restrict__ bias, float* __restrict__ C,
        int M, int N, int K) {
    constexpr int THREADS = (BM / TM) * (BN / TN);
    __shared__ float As[BK][BM + 1];
    __shared__ float Bs[BK][BN];
    int tid = threadIdx.x;
    int block_row = blockIdx.y * BM;
    int block_col = blockIdx.x * BN;
    int tr = tid / (BN / TN);
    int tc = tid % (BN / TN);
    float acc[TM][TN];
#pragma unroll
    for (int i = 0; i < TM; i++)
#pragma unroll
        for (int j = 0; j < TN; j++) acc[i][j] = 0.f;

    for (int k0 = 0; k0 < K; k0 += BK) {
#pragma unroll 4
        for (int i = tid; i < BM * BK; i += THREADS) {
            int r = i / BK, c = i % BK;
            int gr = block_row + r;
            float v = 0.f;
            if (gr < M) {
                v = A[(size_t)gr * K + k0 + c];
                if (BNA) v = fmaf(v, g_scale[k0 + c], g_shift[k0 + c]);
            }
            As[c][r] = v;
        }
#pragma unroll 4
        for (int i = tid; i < BK * BN; i += THREADS) {
            int r = i / BN, c = i % BN;
            int gc = block_col + c;
            Bs[r][c] = (gc < N) ? B[(size_t)(k0 + r) * N + gc] : 0.f;
        }
        __syncthreads();
#pragma unroll
        for (int kk = 0; kk < BK; kk++) {
            float a[TM], b[TN];
#pragma unroll
            for (int i = 0; i < TM; i++) a[i] = As[kk][tr * TM + i];
#pragma unroll
            for (int j = 0; j < TN; j++) b[j] = Bs[kk][tc * TN + j];
#pragma unroll
            for (int i = 0; i < TM; i++)
#pragma unroll
                for (int j = 0; j < TN; j++) acc[i][j] += a[i] * b[j];
        }
        __syncthreads();
    }
#pragma unroll
    for (int i = 0; i < TM; i++) {
        int gr = block_row + tr * TM + i;
        if (gr >= M) continue;
#pragma unroll
        for (int j = 0; j < TN; j++) {
            int gc = block_col + tc * TN + j;
            if (gc >= N) continue;
            float v = acc[i][j];
            if (bias) v += bias[gc];
            C[(size_t)gr * N + gc] = v;
        }
    }
}

// ---------------- CSR build (by dst) ----------------
__global__ void count_k(const int* __restrict__ ei) {
    int j = blockIdx.x * blockDim.x + threadIdx.x;
    if (j >= ET) return;
    int dd = (j < EE) ? ei[EE + j] : (j - EE);
    atomicAdd(&g_deg[dd], 1);
}
__global__ void scan_k() {
    __shared__ int tsum[1024];
    int tid = threadIdx.x;
    const int CH = (NN + 1023) / 1024;
    int b = tid * CH;
    int loc = 0;
    for (int i = 0; i < CH; i++) {
        int idx = b + i;
        if (idx < NN) loc += g_deg[idx];
    }
    tsum[tid] = loc;
    __syncthreads();
    if (tid == 0) {
        int run = 0;
        for (int i = 0; i < 1024; i++) { int t = tsum[i]; tsum[i] = run; run += t; }
        g_off[NN] = run;
    }
    __syncthreads();
    int run = tsum[tid];
    for (int i = 0; i < CH; i++) {
        int idx = b + i;
        if (idx < NN) {
            g_off[idx] = run;
            g_cur[idx] = run;
            run += g_deg[idx];
        }
    }
}
__global__ void scatter_k(const int* __restrict__ ei) {
    int j = blockIdx.x * blockDim.x + threadIdx.x;
    if (j >= ET) return;
    int s, dd;
    if (j < EE) { s = ei[j]; dd = ei[EE + j]; }
    else        { s = j - EE; dd = j - EE; }
    int pos = atomicAdd(&g_cur[dd], 1);
    g_srcs[pos] = s;
}

// ---------------- attention scalars ----------------
__global__ void alar_k(const float* __restrict__ xl,
                       const float* __restrict__ asrc, const float* __restrict__ adst) {
    int gw = (blockIdx.x * blockDim.x + threadIdx.x) >> 5;
    int lane = threadIdx.x & 31;
    if (gw >= NN) return;
    const float* row = xl + (size_t)gw * DIM;
    float s1 = 0.f, s2 = 0.f;
    for (int c = lane; c < DIM; c += 32) {
        float v = row[c];
        s1 += v * asrc[c];
        s2 += v * adst[c];
    }
#pragma unroll
    for (int o = 16; o; o >>= 1) {
        s1 += __shfl_xor_sync(0xffffffffu, s1, o);
        s2 += __shfl_xor_sync(0xffffffffu, s2, o);
    }
    if (lane == 0) { g_al[gw] = s1; g_ar[gw] = s2; }
}

// ---------------- GAT aggregation (warp per node) ----------------
__global__ void __launch_bounds__(256)
gat_agg_k(const float* __restrict__ xl, const float* __restrict__ bias,
          float* __restrict__ out) {
    int node = (blockIdx.x * blockDim.x + threadIdx.x) >> 5;
    int lane = threadIdx.x & 31;
    if (node >= NN) return;
    const int beg = g_off[node], end = g_off[node + 1];
    const float ar_i = g_ar[node];

    float m = -INFINITY;
    for (int j = beg + lane; j < end; j += 32) {
        float e = g_al[g_srcs[j]] + ar_i;
        e = (e > 0.f) ? e : SLOPE * e;
        m = fmaxf(m, e);
    }
#pragma unroll
    for (int o = 16; o; o >>= 1) m = fmaxf(m, __shfl_xor_sync(0xffffffffu, m, o));
    float den = 0.f;
    for (int j = beg + lane; j < end; j += 32) {
        float e = g_al[g_srcs[j]] + ar_i;
        e = (e > 0.f) ? e : SLOPE * e;
        den += expf(e - m);
    }
#pragma unroll
    for (int o = 16; o; o >>= 1) den += __shfl_xor_sync(0xffffffffu, den, o);
    const float inv_den = 1.f / (den + 1e-16f);

    float4 a[6];
#pragma unroll
    for (int i = 0; i < 6; i++) a[i] = make_float4(0.f, 0.f, 0.f, 0.f);

    for (int chunk = beg; chunk < end; chunk += 32) {
        int idx = chunk + lane;
        float cf = 0.f; int s = 0;
        if (idx < end) {
            s = g_srcs[idx];
            float e = g_al[s] + ar_i;
            e = (e > 0.f) ? e : SLOPE * e;
            cf = expf(e - m) * inv_den;
        }
        int cnt = min(32, end - chunk);
        for (int t = 0; t < cnt; t++) {
            float w = __shfl_sync(0xffffffffu, cf, t);
            int si = __shfl_sync(0xffffffffu, s, t);
            const float4* row = (const float4*)(xl + (size_t)si * DIM);
#pragma unroll
            for (int i = 0; i < 6; i++) {
                float4 v = row[lane + 32 * i];
                a[i].x += w * v.x; a[i].y += w * v.y;
                a[i].z += w * v.z; a[i].w += w * v.w;
            }
        }
    }
    float4* orow = (float4*)(out + (size_t)node * DIM);
    const float4* b4 = (const float4*)bias;
#pragma unroll
    for (int i = 0; i < 6; i++) {
        float4 bv = b4[lane + 32 * i];
        float4 v = a[i];
        v.x += bv.x; v.y += bv.y; v.z += bv.z; v.w += bv.w;
        orow[lane + 32 * i] = v;
    }
}

// ---------------- masked CE + accuracy ----------------
__global__ void ce_k(const float* __restrict__ logits, const int* __restrict__ target,
                     int accbase) {
    int gw = (blockIdx.x * blockDim.x + threadIdx.x) >> 5;
    int lane = threadIdx.x & 31;
    if (gw >= NN) return;
    float v = logits[(size_t)gw * CLS + lane];
    float mx = v;
#pragma unroll
    for (int o = 16; o; o >>= 1) mx = fmaxf(mx, __shfl_xor_sync(0xffffffffu, mx, o));
    float ex = expf(v - mx);
    float sum = ex;
#pragma unroll
    for (int o = 16; o; o >>= 1) sum += __shfl_xor_sync(0xffffffffu, sum, o);
    int t = target[gw];
    if (t < 0) return;
    unsigned mask = __ballot_sync(0xffffffffu, v == mx);
    int amax = __ffs(mask) - 1;
    if (lane == t) {
        float nll = -(v - mx - logf(sum));
        atomicAdd(&g_acc[accbase + 0], nll);
    }
    if (lane == 0) {
        atomicAdd(&g_acc[accbase + 1], (amax == t) ? 1.f : 0.f);
        atomicAdd(&g_acc[accbase + 2], 1.f);
    }
}
__global__ void final_k(float* __restrict__ out_scal) {
    out_scal[0] = g_acc[0] / g_acc[2] + g_acc[3] / g_acc[5];
    out_scal[1] = g_acc[1] / g_acc[2];
    out_scal[2] = g_acc[4] / g_acc[5];
}

// ---------------- driver ----------------
extern "C" void kernel_launch(void* const* d_in, const int* in_sizes, int n_in,
                              void* d_out, int out_size) {
    const float* x     = (const float*)d_in[0];
    const int*   ei    = (const int*)d_in[1];
    const int*   target= (const int*)d_in[2];
    const float* gamma = (const float*)d_in[3];
    const float* beta  = (const float*)d_in[4];
    const float* W1    = (const float*)d_in[5];
    const float* as1   = (const float*)d_in[6];
    const float* ad1   = (const float*)d_in[7];
    const float* b1    = (const float*)d_in[8];
    const float* W2    = (const float*)d_in[9];
    const float* as2   = (const float*)d_in[10];
    const float* ad2   = (const float*)d_in[11];
    const float* b2    = (const float*)d_in[12];
    const float* poolW = (const float*)d_in[13];
    const float* poolb = (const float*)d_in[14];
    const float* dirW  = (const float*)d_in[15];
    const float* dirb  = (const float*)d_in[16];
    float* out = (float*)d_out;

    const size_t OFF_DIR  = (size_t)NN * DIM;
    const size_t OFF_POOL = OFF_DIR + (size_t)NN * CLS;
    const size_t OFF_SCAL = OFF_POOL + (size_t)NN * CLS;

    float *p_xl, *p_h1;
    cudaGetSymbolAddress((void**)&p_xl, g_xl);
    cudaGetSymbolAddress((void**)&p_h1, g_h1);

    init_k<<<(NN + 255) / 256, 256>>>();

    // CSR by dst (independent of BN)
    count_k<<<(ET + 255) / 256, 256>>>(ei);
    scan_k<<<1, 1024>>>();
    scatter_k<<<(ET + 255) / 256, 256>>>(ei);

    // BatchNorm stats -> scale/shift (folded into all consumers of xn)
    bn_stats_k<<<dim3((IND + 255) / 256, (NN + 127) / 128), 256>>>(x);
    bn_finalize_k<<<(IND + 255) / 256, 256>>>(gamma, beta);

    // direct head: BN(x) @ dir_W + dir_b (BN folded in A load)
    sgemm_k<128, 32, 32, 8, 2, true><<<dim3(1, (NN + 127) / 128), 256>>>(
        x, dirW, dirb, out + OFF_DIR, NN, CLS, IND);

    // ---- GAT layer 1: xl1 = BN(x) @ W1 ----
    tf32gemm3x_k<<<dim3(DIM / 128, (NN + 127) / 128), 128>>>(
        x, IND, 1, (const float*)nullptr, 0, 0, W1, p_xl, NN, DIM);
    alar_k<<<(NN * 32 + 255) / 256, 256>>>(p_xl, as1, ad1);
    gat_agg_k<<<(NN * 32 + 255) / 256, 256>>>(p_xl, b1, p_h1);

    // ---- GAT layer 2 (fused K): xl2 = h1 @ W2[0:768] + BN(x) @ W2[768:3072] ----
    tf32gemm3x_k<<<dim3(DIM / 128, (NN + 127) / 128), 128>>>(
        p_h1, DIM, 0, x, IND, 1, W2, p_xl, NN, DIM);
    alar_k<<<(NN * 32 + 255) / 256, 256>>>(p_xl, as2, ad2);
    gat_agg_k<<<(NN * 32 + 255) / 256, 256>>>(p_xl, b2, out /* h2 */);

    // pooler: h2 @ pool_W + pool_b
    sgemm_k<128, 32, 32, 8, 2, false><<<dim3(1, (NN + 127) / 128), 256>>>(
        out, poolW, poolb, out + OFF_POOL, NN, CLS, DIM);

    // losses + accuracies
    ce_k<<<(NN * 32 + 255) / 256, 256>>>(out + OFF_POOL, target, 0);
    ce_k<<<(NN * 32 + 255) / 256, 256>>>(out + OFF_DIR, target, 3);
    final_k<<<1, 1>>>(out + OFF_SCAL);
}

// round 7
// speedup vs baseline: 1.0336x; 1.0336x over previous
#include <cuda_runtime.h>
#include <math.h>
#include <stdint.h>

#define NN 20000
#define EE 160000
#define ET (EE + NN)
#define DIM 768
#define IND 2304
#define CLS 32
#define EPS_BN 1e-5f
#define SLOPE 0.2f

// ---------------- scratch (device globals; no allocation) ----------------
__device__ float g_xl[(size_t)NN * DIM];
__device__ float g_h1[(size_t)NN * DIM];
__device__ float g_al[NN];
__device__ float g_ar[NN];
__device__ float g_stats[2 * IND];
__device__ float g_scale[IND];
__device__ float g_shift[IND];
__device__ int   g_deg[NN];
__device__ int   g_off[NN + 1];
__device__ int   g_cur[NN];
__device__ int   g_srcs[ET];
__device__ float g_acc[8];

// ---------------- init ----------------
__global__ void init_k() {
    int i = blockIdx.x * blockDim.x + threadIdx.x;
    if (i < NN) g_deg[i] = 0;
    if (i < 2 * IND) g_stats[i] = 0.f;
    if (i < 8) g_acc[i] = 0.f;
}

// ---------------- BatchNorm stats ----------------
__global__ void bn_stats_k(const float* __restrict__ x) {
    int c = blockIdx.x * blockDim.x + threadIdx.x;
    if (c >= IND) return;
    int r0 = blockIdx.y * 128;
    int r1 = min(r0 + 128, NN);
    float s = 0.f, s2 = 0.f;
    for (int r = r0; r < r1; r++) {
        float v = x[(size_t)r * IND + c];
        s += v; s2 += v * v;
    }
    atomicAdd(&g_stats[c], s);
    atomicAdd(&g_stats[IND + c], s2);
}
__global__ void bn_finalize_k(const float* __restrict__ gamma, const float* __restrict__ beta) {
    int c = blockIdx.x * blockDim.x + threadIdx.x;
    if (c >= IND) return;
    float mu = g_stats[c] / (float)NN;
    float var = g_stats[IND + c] / (float)NN - mu * mu;
    float inv = 1.f / sqrtf(var + EPS_BN);
    float sc = gamma[c] * inv;
    g_scale[c] = sc;
    g_shift[c] = beta[c] - mu * sc;
}

// ---------------- tf32 helpers ----------------
__device__ __forceinline__ uint32_t f2tf(float f) {
    uint32_t u;
    asm("cvt.rna.tf32.f32 %0, %1;" : "=r"(u) : "f"(f));
    return u;
}
__device__ __forceinline__ void mma_tf32(float* d, const uint32_t* a, const uint32_t* b) {
    asm volatile(
        "mma.sync.aligned.m16n8k8.row.col.f32.tf32.tf32.f32 "
        "{%0,%1,%2,%3},{%4,%5,%6,%7},{%8,%9},{%0,%1,%2,%3};"
        : "+f"(d[0]), "+f"(d[1]), "+f"(d[2]), "+f"(d[3])
        : "r"(a[0]), "r"(a[1]), "r"(a[2]), "r"(a[3]), "r"(b[0]), "r"(b[1]));
}

// ---------------- 3xTF32 GEMM: cp.async double-buffered, BN fold at frag load
// C[M,N] = [A1;A2][M, K1+K2] @ B[K1+K2, N]. BM=BN=128, BK=16, 4 warps 64x64.
#define AST 20
__global__ void __launch_bounds__(128)
tf32gemm3x_k(const float* __restrict__ A1, int K1, int bn1,
             const float* __restrict__ A2, int K2, int bn2,
             const float* __restrict__ B, float* __restrict__ C,
             int M, int N) {
    __shared__ float Asm[2][128 * AST];
    __shared__ float Bsm[2][16 * 128];
    const int tid = threadIdx.x;
    const int wid = tid >> 5, lane = tid & 31;
    const int bm0 = blockIdx.y * 128, bn0 = blockIdx.x * 128;
    const int wm0 = (wid >> 1) * 64;
    const int wn0 = (wid & 1) * 64;
    const int r0 = lane >> 2, c0 = lane & 3;
    const int bsw = c0 * 8;

    float acc[4][8][4];
#pragma unroll
    for (int i = 0; i < 4; i++)
#pragma unroll
        for (int j = 0; j < 8; j++)
#pragma unroll
            for (int v = 0; v < 4; v++) acc[i][j][v] = 0.f;

    const int KT = (K1 + K2) / 16;

    auto issue = [&](int kt, int buf) {
        const int k0 = kt * 16;
        const float* Ap; int lda, ka;
        if (k0 < K1) { Ap = A1; lda = K1; ka = k0; }
        else         { Ap = A2; lda = K2; ka = k0 - K1; }
#pragma unroll
        for (int it = 0; it < 4; it++) {
            int idx = it * 128 + tid;
            int m = idx >> 2, kc = (idx & 3) * 4;
            int gr = bm0 + m;
            int grs = (gr < M) ? gr : 0;   // keep address in-range; sz=0 zero-fills
            const float* src = Ap + (size_t)grs * lda + ka + kc;
            uint32_t dst = (uint32_t)__cvta_generic_to_shared(&Asm[buf][m * AST + kc]);
            int sz = (gr < M) ? 16 : 0;
            asm volatile("cp.async.cg.shared.global [%0], [%1], 16, %2;\n"
                         :: "r"(dst), "l"(src), "r"(sz));
        }
#pragma unroll
        for (int it = 0; it < 4; it++) {
            int idx = it * 128 + tid;
            int kk = idx >> 5, n4 = (idx & 31) * 4;
            int col = n4 ^ ((kk & 3) * 8);
            const float* src = B + (size_t)(k0 + kk) * N + bn0 + n4;
            uint32_t dst = (uint32_t)__cvta_generic_to_shared(&Bsm[buf][kk * 128 + col]);
            asm volatile("cp.async.cg.shared.global [%0], [%1], 16;\n"
                         :: "r"(dst), "l"(src));
        }
        asm volatile("cp.async.commit_group;\n" ::: "memory");
    };

    issue(0, 0);
    int buf = 0;
    for (int kt = 0; kt < KT; kt++) {
        if (kt + 1 < KT) {
            issue(kt + 1, buf ^ 1);
            asm volatile("cp.async.wait_group 1;\n" ::: "memory");
        } else {
            asm volatile("cp.async.wait_group 0;\n" ::: "memory");
        }
        __syncthreads();

        const int k0 = kt * 16;
        int dobn, scoff;
        if (k0 < K1) { dobn = bn1; scoff = k0; }
        else         { dobn = bn2; scoff = k0 - K1; }

        const float* __restrict__ As = Asm[buf];
        const float* __restrict__ Bs = Bsm[buf];

#pragma unroll
        for (int sub = 0; sub < 2; sub++) {
            const int kb = sub * 8;
            float sc0 = 1.f, sh0 = 0.f, sc1 = 1.f, sh1 = 0.f;
            if (dobn) {
                sc0 = g_scale[scoff + kb + c0];     sh0 = g_shift[scoff + kb + c0];
                sc1 = g_scale[scoff + kb + c0 + 4]; sh1 = g_shift[scoff + kb + c0 + 4];
            }
            uint32_t ah[4][4], al_[4][4];
#pragma unroll
            for (int mt = 0; mt < 4; mt++) {
                int ra = (wm0 + mt * 16 + r0) * AST + kb + c0;
                int rb = ra + 8 * AST;
                float v0 = fmaf(As[ra],     sc0, sh0);
                float v1 = fmaf(As[rb],     sc0, sh0);
                float v2 = fmaf(As[ra + 4], sc1, sh1);
                float v3 = fmaf(As[rb + 4], sc1, sh1);
                ah[mt][0] = f2tf(v0); al_[mt][0] = f2tf(v0 - __uint_as_float(ah[mt][0]));
                ah[mt][1] = f2tf(v1); al_[mt][1] = f2tf(v1 - __uint_as_float(ah[mt][1]));
                ah[mt][2] = f2tf(v2); al_[mt][2] = f2tf(v2 - __uint_as_float(ah[mt][2]));
                ah[mt][3] = f2tf(v3); al_[mt][3] = f2tf(v3 - __uint_as_float(ah[mt][3]));
            }
#pragma unroll
            for (int half = 0; half < 2; half++) {
                uint32_t bh[4][2], bl[4][2];
#pragma unroll
                for (int q = 0; q < 4; q++) {
                    int nt = half * 4 + q;
                    int nb = (wn0 + nt * 8 + r0) ^ bsw;
                    int i0 = (kb + c0) * 128 + nb;
                    int i1 = i0 + 4 * 128;
                    float w0 = Bs[i0], w1 = Bs[i1];
                    bh[q][0] = f2tf(w0); bl[q][0] = f2tf(w0 - __uint_as_float(bh[q][0]));
                    bh[q][1] = f2tf(w1); bl[q][1] = f2tf(w1 - __uint_as_float(bh[q][1]));
                }
#pragma unroll
                for (int mt = 0; mt < 4; mt++)
#pragma unroll
                    for (int q = 0; q < 4; q++) {
                        float* a = acc[mt][half * 4 + q];
                        mma_tf32(a, al_[mt], bh[q]);
                        mma_tf32(a, ah[mt], bl[q]);
                        mma_tf32(a, ah[mt], bh[q]);
                    }
            }
        }
        __syncthreads();
        buf ^= 1;
    }

    // epilogue
#pragma unroll
    for (int mt = 0; mt < 4; mt++) {
        int gr0 = bm0 + wm0 + mt * 16 + r0;
        int gr1 = gr0 + 8;
#pragma unroll
        for (int nt = 0; nt < 8; nt++) {
            int gc = bn0 + wn0 + nt * 8 + 2 * c0;
            if (gr0 < M)
                *(float2*)(C + (size_t)gr0 * N + gc) = make_float2(acc[mt][nt][0], acc[mt][nt][1]);
            if (gr1 < M)
                *(float2*)(C + (size_t)gr1 * N + gc) = make_float2(acc[mt][nt][2], acc[mt][nt][3]);
        }
    }
}

// ---------------- SIMT SGEMM (small-N heads), optional BN fold on A ----------
template<int BM, int BN, int BK, int TM, int TN, bool BNA>
__global__ void __launch_bounds__((BM / TM) * (BN / TN))
sgemm_k(const float* __restrict__ A, const float* __restrict__ B,
        const float* __restrict__ bias, float* __restrict__ C,
        int M, int N, int K) {
    constexpr int THREADS = (BM / TM) * (BN / TN);
    __shared__ float As[BK][BM + 1];
    __shared__ float Bs[BK][BN];
    int tid = threadIdx.x;
    int block_row = blockIdx.y * BM;
    int block_col = blockIdx.x * BN;
    int tr = tid / (BN / TN);
    int tc = tid % (BN / TN);
    float acc[TM][TN];
#pragma unroll
    for (int i = 0; i < TM; i++)
#pragma unroll
        for (int j = 0; j < TN; j++) acc[i][j] = 0.f;

    for (int k0 = 0; k0 < K; k0 += BK) {
#pragma unroll 4
        for (int i = tid; i < BM * BK; i += THREADS) {
            int r = i / BK, c = i % BK;
            int gr = block_row + r;
            float v = 0.f;
            if (gr < M) {
                v = A[(size_t)gr * K + k0 + c];
                if (BNA) v = fmaf(v, g_scale[k0 + c], g_shift[k0 + c]);
            }
            As[c][r] = v;
        }
#pragma unroll 4
        for (int i = tid; i < BK * BN; i += THREADS) {
            int r = i / BN, c = i % BN;
            int gc = block_col + c;
            Bs[r][c] = (gc < N) ? B[(size_t)(k0 + r) * N + gc] : 0.f;
        }
        __syncthreads();
#pragma unroll
        for (int kk = 0; kk < BK; kk++) {
            float a[TM], b[TN];
#pragma unroll
            for (int i = 0; i < TM; i++) a[i] = As[kk][tr * TM + i];
#pragma unroll
            for (int j = 0; j < TN; j++) b[j] = Bs[kk][tc * TN + j];
#pragma unroll
            for (int i = 0; i < TM; i++)
#pragma unroll
                for (int j = 0; j < TN; j++) acc[i][j] += a[i] * b[j];
        }
        __syncthreads();
    }
#pragma unroll
    for (int i = 0; i < TM; i++) {
        int gr = block_row + tr * TM + i;
        if (gr >= M) continue;
#pragma unroll
        for (int j = 0; j < TN; j++) {
            int gc = block_col + tc * TN + j;
            if (gc >= N) continue;
            float v = acc[i][j];
            if (bias) v += bias[gc];
            C[(size_t)gr * N + gc] = v;
        }
    }
}

// ---------------- CSR build (by dst) ----------------
__global__ void count_k(const int* __restrict__ ei) {
    int j = blockIdx.x * blockDim.x + threadIdx.x;
    if (j >= ET) return;
    int dd = (j < EE) ? ei[EE + j] : (j - EE);
    atomicAdd(&g_deg[dd], 1);
}
__global__ void scan_k() {
    __shared__ int tsum[1024];
    int tid = threadIdx.x;
    const int CH = (NN + 1023) / 1024;
    int b = tid * CH;
    int loc = 0;
    for (int i = 0; i < CH; i++) {
        int idx = b + i;
        if (idx < NN) loc += g_deg[idx];
    }
    tsum[tid] = loc;
    __syncthreads();
    if (tid == 0) {
        int run = 0;
        for (int i = 0; i < 1024; i++) { int t = tsum[i]; tsum[i] = run; run += t; }
        g_off[NN] = run;
    }
    __syncthreads();
    int run = tsum[tid];
    for (int i = 0; i < CH; i++) {
        int idx = b + i;
        if (idx < NN) {
            g_off[idx] = run;
            g_cur[idx] = run;
            run += g_deg[idx];
        }
    }
}
__global__ void scatter_k(const int* __restrict__ ei) {
    int j = blockIdx.x * blockDim.x + threadIdx.x;
    if (j >= ET) return;
    int s, dd;
    if (j < EE) { s = ei[j]; dd = ei[EE + j]; }
    else        { s = j - EE; dd = j - EE; }
    int pos = atomicAdd(&g_cur[dd], 1);
    g_srcs[pos] = s;
}

// ---------------- attention scalars ----------------
__global__ void alar_k(const float* __restrict__ xl,
                       const float* __restrict__ asrc, const float* __restrict__ adst) {
    int gw = (blockIdx.x * blockDim.x + threadIdx.x) >> 5;
    int lane = threadIdx.x & 31;
    if (gw >= NN) return;
    const float* row = xl + (size_t)gw * DIM;
    float s1 = 0.f, s2 = 0.f;
    for (int c = lane; c < DIM; c += 32) {
        float v = row[c];
        s1 += v * asrc[c];
        s2 += v * adst[c];
    }
#pragma unroll
    for (int o = 16; o; o >>= 1) {
        s1 += __shfl_xor_sync(0xffffffffu, s1, o);
        s2 += __shfl_xor_sync(0xffffffffu, s2, o);
    }
    if (lane == 0) { g_al[gw] = s1; g_ar[gw] = s2; }
}

// ---------------- GAT aggregation (warp per node) ----------------
__global__ void __launch_bounds__(256)
gat_agg_k(const float* __restrict__ xl, const float* __restrict__ bias,
          float* __restrict__ out) {
    int node = (blockIdx.x * blockDim.x + threadIdx.x) >> 5;
    int lane = threadIdx.x & 31;
    if (node >= NN) return;
    const int beg = g_off[node], end = g_off[node + 1];
    const float ar_i = g_ar[node];

    float m = -INFINITY;
    for (int j = beg + lane; j < end; j += 32) {
        float e = g_al[g_srcs[j]] + ar_i;
        e = (e > 0.f) ? e : SLOPE * e;
        m = fmaxf(m, e);
    }
#pragma unroll
    for (int o = 16; o; o >>= 1) m = fmaxf(m, __shfl_xor_sync(0xffffffffu, m, o));
    float den = 0.f;
    for (int j = beg + lane; j < end; j += 32) {
        float e = g_al[g_srcs[j]] + ar_i;
        e = (e > 0.f) ? e : SLOPE * e;
        den += expf(e - m);
    }
#pragma unroll
    for (int o = 16; o; o >>= 1) den += __shfl_xor_sync(0xffffffffu, den, o);
    const float inv_den = 1.f / (den + 1e-16f);

    float4 a[6];
#pragma unroll
    for (int i = 0; i < 6; i++) a[i] = make_float4(0.f, 0.f, 0.f, 0.f);

    for (int chunk = beg; chunk < end; chunk += 32) {
        int idx = chunk + lane;
        float cf = 0.f; int s = 0;
        if (idx < end) {
            s = g_srcs[idx];
            float e = g_al[s] + ar_i;
            e = (e > 0.f) ? e : SLOPE * e;
            cf = expf(e - m) * inv_den;
        }
        int cnt = min(32, end - chunk);
        for (int t = 0; t < cnt; t++) {
            float w = __shfl_sync(0xffffffffu, cf, t);
            int si = __shfl_sync(0xffffffffu, s, t);
            const float4* row = (const float4*)(xl + (size_t)si * DIM);
#pragma unroll
            for (int i = 0; i < 6; i++) {
                float4 v = row[lane + 32 * i];
                a[i].x += w * v.x; a[i].y += w * v.y;
                a[i].z += w * v.z; a[i].w += w * v.w;
            }
        }
    }
    float4* orow = (float4*)(out + (size_t)node * DIM);
    const float4* b4 = (const float4*)bias;
#pragma unroll
    for (int i = 0; i < 6; i++) {
        float4 bv = b4[lane + 32 * i];
        float4 v = a[i];
        v.x += bv.x; v.y += bv.y; v.z += bv.z; v.w += bv.w;
        orow[lane + 32 * i] = v;
    }
}

// ---------------- masked CE + accuracy ----------------
__global__ void ce_k(const float* __restrict__ logits, const int* __restrict__ target,
                     int accbase) {
    int gw = (blockIdx.x * blockDim.x + threadIdx.x) >> 5;
    int lane = threadIdx.x & 31;
    if (gw >= NN) return;
    float v = logits[(size_t)gw * CLS + lane];
    float mx = v;
#pragma unroll
    for (int o = 16; o; o >>= 1) mx = fmaxf(mx, __shfl_xor_sync(0xffffffffu, mx, o));
    float ex = expf(v - mx);
    float sum = ex;
#pragma unroll
    for (int o = 16; o; o >>= 1) sum += __shfl_xor_sync(0xffffffffu, sum, o);
    int t = target[gw];
    if (t < 0) return;
    unsigned mask = __ballot_sync(0xffffffffu, v == mx);
    int amax = __ffs(mask) - 1;
    if (lane == t) {
        float nll = -(v - mx - logf(sum));
        atomicAdd(&g_acc[accbase + 0], nll);
    }
    if (lane == 0) {
        atomicAdd(&g_acc[accbase + 1], (amax == t) ? 1.f : 0.f);
        atomicAdd(&g_acc[accbase + 2], 1.f);
    }
}
__global__ void final_k(float* __restrict__ out_scal) {
    out_scal[0] = g_acc[0] / g_acc[2] + g_acc[3] / g_acc[5];
    out_scal[1] = g_acc[1] / g_acc[2];
    out_scal[2] = g_acc[4] / g_acc[5];
}

// ---------------- driver ----------------
extern "C" void kernel_launch(void* const* d_in, const int* in_sizes, int n_in,
                              void* d_out, int out_size) {
    const float* x     = (const float*)d_in[0];
    const int*   ei    = (const int*)d_in[1];
    const int*   target= (const int*)d_in[2];
    const float* gamma = (const float*)d_in[3];
    const float* beta  = (const float*)d_in[4];
    const float* W1    = (const float*)d_in[5];
    const float* as1   = (const float*)d_in[6];
    const float* ad1   = (const float*)d_in[7];
    const float* b1    = (const float*)d_in[8];
    const float* W2    = (const float*)d_in[9];
    const float* as2   = (const float*)d_in[10];
    const float* ad2   = (const float*)d_in[11];
    const float* b2    = (const float*)d_in[12];
    const float* poolW = (const float*)d_in[13];
    const float* poolb = (const float*)d_in[14];
    const float* dirW  = (const float*)d_in[15];
    const float* dirb  = (const float*)d_in[16];
    float* out = (float*)d_out;

    const size_t OFF_DIR  = (size_t)NN * DIM;
    const size_t OFF_POOL = OFF_DIR + (size_t)NN * CLS;
    const size_t OFF_SCAL = OFF_POOL + (size_t)NN * CLS;

    float *p_xl, *p_h1;
    cudaGetSymbolAddress((void**)&p_xl, g_xl);
    cudaGetSymbolAddress((void**)&p_h1, g_h1);

    init_k<<<(NN + 255) / 256, 256>>>();

    // CSR by dst
    count_k<<<(ET + 255) / 256, 256>>>(ei);
    scan_k<<<1, 1024>>>();
    scatter_k<<<(ET + 255) / 256, 256>>>(ei);

    // BatchNorm stats -> scale/shift (folded into consumers)
    bn_stats_k<<<dim3((IND + 255) / 256, (NN + 127) / 128), 256>>>(x);
    bn_finalize_k<<<(IND + 255) / 256, 256>>>(gamma, beta);

    // direct head: BN(x) @ dir_W + dir_b
    sgemm_k<128, 32, 32, 8, 2, true><<<dim3(1, (NN + 127) / 128), 256>>>(
        x, dirW, dirb, out + OFF_DIR, NN, CLS, IND);

    // ---- GAT layer 1: xl1 = BN(x) @ W1 ----
    tf32gemm3x_k<<<dim3(DIM / 128, (NN + 127) / 128), 128>>>(
        x, IND, 1, (const float*)nullptr, 0, 0, W1, p_xl, NN, DIM);
    alar_k<<<(NN * 32 + 255) / 256, 256>>>(p_xl, as1, ad1);
    gat_agg_k<<<(NN * 32 + 255) / 256, 256>>>(p_xl, b1, p_h1);

    // ---- GAT layer 2 (fused K): xl2 = h1 @ W2[0:768] + BN(x) @ W2[768:3072] ----
    tf32gemm3x_k<<<dim3(DIM / 128, (NN + 127) / 128), 128>>>(
        p_h1, DIM, 0, x, IND, 1, W2, p_xl, NN, DIM);
    alar_k<<<(NN * 32 + 255) / 256, 256>>>(p_xl, as2, ad2);
    gat_agg_k<<<(NN * 32 + 255) / 256, 256>>>(p_xl, b2, out /* h2 */);

    // pooler: h2 @ pool_W + pool_b
    sgemm_k<128, 32, 32, 8, 2, false><<<dim3(1, (NN + 127) / 128), 256>>>(
        out, poolW, poolb, out + OFF_POOL, NN, CLS, DIM);

    // losses + accuracies
    ce_k<<<(NN * 32 + 255) / 256, 256>>>(out + OFF_POOL, target, 0);
    ce_k<<<(NN * 32 + 255) / 256, 256>>>(out + OFF_DIR, target, 3);
    final_k<<<1, 1>>>(out + OFF_SCAL);
}